// round 1
// baseline (speedup 1.0000x reference)
#include <cuda_runtime.h>
#include <cstdint>
#include <cstddef>

// ---------------- problem constants ----------------
#define D_MODEL  1024
#define D_STATE  16
#define D_CONV   4
#define D_INNER  2048
#define DT_RANK  64
#define BATCH    2
#define SEQ      2048
#define NROWS    (BATCH * SEQ)          // 4096
#define DBC_COLS (DT_RANK + 2 * D_STATE) // 96

// ---------------- scratch (static device globals; no allocation) ----------------
__device__ float g_xr [(size_t)NROWS * (2 * D_INNER)];  // 64 MB: cols [0,2048)=xb, [2048,4096)=res
__device__ float g_u  [(size_t)NROWS * D_INNER];        // 32 MB
__device__ float g_dbc[(size_t)NROWS * DBC_COLS];       // 1.5 MB
__device__ float g_dt [(size_t)NROWS * D_INNER];        // 32 MB
__device__ float g_y  [(size_t)NROWS * D_INNER];        // 32 MB (gated y_ssm)

// ---------------- helpers ----------------
__device__ __forceinline__ float silu_f(float x) {
    return x / (1.0f + __expf(-x));
}
__device__ __forceinline__ float softplus_f(float x) {
    return (x > 20.0f) ? x : log1pf(__expf(x));
}

// ---------------- generic tiled SGEMM: C[M,N] = A[M,K(lda)] * B[K,N] ----------------
// mode 0: plain store. mode 1: softplus(acc + bias[col]).
#define BM 128
#define BN 128
#define BKT 8
__global__ __launch_bounds__(256) void sgemm_k(
    const float* __restrict__ A, int lda,
    const float* __restrict__ B,
    const float* __restrict__ bias,
    float* __restrict__ C,
    int M, int N, int K, int mode)
{
    __shared__ float As[BKT][BM];
    __shared__ float Bs[BKT][BN];

    const int tid = threadIdx.x;
    const int tx  = tid & 15;     // 0..15 -> N direction
    const int ty  = tid >> 4;     // 0..15 -> M direction
    const int mBase = blockIdx.y * BM;
    const int nBase = blockIdx.x * BN;

    // A tile loader: 128 rows x 8 cols, 4 elems/thread
    const int aRow = tid >> 1;         // 0..127
    const int aCol = (tid & 1) * 4;    // 0 or 4
    // B tile loader: 8 rows x 128 cols, 4 elems/thread
    const int bRow = tid >> 5;         // 0..7
    const int bCol = (tid & 31) * 4;   // 0..124

    float acc[8][8];
#pragma unroll
    for (int i = 0; i < 8; i++)
#pragma unroll
        for (int j = 0; j < 8; j++) acc[i][j] = 0.0f;

    for (int k0 = 0; k0 < K; k0 += BKT) {
        // load A tile (M always multiple of 128 here; K multiple of 8)
#pragma unroll
        for (int j = 0; j < 4; j++) {
            int gr = mBase + aRow;
            int gc = k0 + aCol + j;
            As[aCol + j][aRow] = A[(size_t)gr * lda + gc];
        }
        // load B tile with N guard (x_proj has N=96)
#pragma unroll
        for (int j = 0; j < 4; j++) {
            int gc = nBase + bCol + j;
            float v = (gc < N) ? B[(size_t)(k0 + bRow) * N + gc] : 0.0f;
            Bs[bRow][bCol + j] = v;
        }
        __syncthreads();

#pragma unroll
        for (int kk = 0; kk < BKT; kk++) {
            float am[8], bn[8];
#pragma unroll
            for (int i = 0; i < 8; i++) am[i] = As[kk][ty * 8 + i];
#pragma unroll
            for (int j = 0; j < 8; j++) bn[j] = Bs[kk][tx * 8 + j];
#pragma unroll
            for (int i = 0; i < 8; i++)
#pragma unroll
                for (int j = 0; j < 8; j++)
                    acc[i][j] = fmaf(am[i], bn[j], acc[i][j]);
        }
        __syncthreads();
    }

#pragma unroll
    for (int i = 0; i < 8; i++) {
        int row = mBase + ty * 8 + i;
#pragma unroll
        for (int j = 0; j < 8; j++) {
            int col = nBase + tx * 8 + j;
            if (col < N) {
                float v = acc[i][j];
                if (mode == 1) v = softplus_f(v + bias[col]);
                C[(size_t)row * N + col] = v;
            }
        }
    }
}

// ---------------- causal depthwise conv1d + silu ----------------
// u[b,l,d] = silu( conv_b[d] + sum_{k=0..3, l-3+k>=0} xb[b,l-3+k,d] * conv_w[d,k] )
__global__ void conv_silu_k(const float* __restrict__ conv_w,
                            const float* __restrict__ conv_b)
{
    size_t idx = (size_t)blockIdx.x * blockDim.x + threadIdx.x;
    if (idx >= (size_t)NROWS * D_INNER) return;
    int d = (int)(idx % D_INNER);
    int l = (int)((idx / D_INNER) % SEQ);
    int b = (int)(idx / ((size_t)D_INNER * SEQ));

    float acc = conv_b[d];
    const float w0 = conv_w[d * 4 + 0];
    const float w1 = conv_w[d * 4 + 1];
    const float w2 = conv_w[d * 4 + 2];
    const float w3 = conv_w[d * 4 + 3];
    const size_t base = ((size_t)b * SEQ) * (2 * D_INNER) + d; // xb part of g_xr
    const size_t rs = 2 * D_INNER;
    if (l - 3 >= 0) acc = fmaf(g_xr[base + (size_t)(l - 3) * rs], w0, acc);
    if (l - 2 >= 0) acc = fmaf(g_xr[base + (size_t)(l - 2) * rs], w1, acc);
    if (l - 1 >= 0) acc = fmaf(g_xr[base + (size_t)(l - 1) * rs], w2, acc);
    acc = fmaf(g_xr[base + (size_t)l * rs], w3, acc);

    g_u[((size_t)b * SEQ + l) * D_INNER + d] = silu_f(acc);
}

// ---------------- selective scan ----------------
// thread = (d, n) pair. 16 lanes per d; 16 d per 256-thread block.
// grid = (D_INNER/16, BATCH)
__global__ __launch_bounds__(256) void scan_k(
    const float* __restrict__ A_log,
    const float* __restrict__ Dv)
{
    const int b = blockIdx.y;
    const int d = blockIdx.x * 16 + (threadIdx.x >> 4);
    const int n = threadIdx.x & 15;

    const float A  = -__expf(A_log[d * D_STATE + n]);
    const float Dd = Dv[d];
    float h = 0.0f;

    const size_t row0   = (size_t)b * SEQ;
    const size_t baseRU = row0 * D_INNER + d;              // dt / u / y index
    const size_t baseBC = row0 * DBC_COLS + DT_RANK + n;   // B at +64, C at +80
    const size_t baseRes = row0 * (2 * D_INNER) + D_INNER + d;

    // prefetch l = 0
    float dt = g_dt[baseRU];
    float u  = g_u [baseRU];
    float Bn = g_dbc[baseBC];
    float Cn = g_dbc[baseBC + D_STATE];

    for (int l = 0; l < SEQ; l++) {
        // prefetch next step to hide DRAM latency of the serial chain
        float dt2 = 0.f, u2 = 0.f, B2 = 0.f, C2 = 0.f;
        if (l + 1 < SEQ) {
            size_t o  = baseRU + (size_t)(l + 1) * D_INNER;
            size_t ob = baseBC + (size_t)(l + 1) * DBC_COLS;
            dt2 = g_dt[o];
            u2  = g_u [o];
            B2  = g_dbc[ob];
            C2  = g_dbc[ob + D_STATE];
        }

        float dA = __expf(dt * A);
        h = fmaf(h, dA, (dt * u) * Bn);
        float v = h * Cn;

        // reduce over the 16 state lanes (stays within 16-lane halves of the warp)
        v += __shfl_xor_sync(0xffffffffu, v, 8);
        v += __shfl_xor_sync(0xffffffffu, v, 4);
        v += __shfl_xor_sync(0xffffffffu, v, 2);
        v += __shfl_xor_sync(0xffffffffu, v, 1);

        if (n == 0) {
            float r = g_xr[baseRes + (size_t)l * (2 * D_INNER)];
            float y = (v + Dd * u) * silu_f(r);
            g_y[baseRU + (size_t)l * D_INNER] = y;
        }

        dt = dt2; u = u2; Bn = B2; Cn = C2;
    }
}

// ---------------- launch ----------------
extern "C" void kernel_launch(void* const* d_in, const int* in_sizes, int n_in,
                              void* d_out, int out_size)
{
    const float* x          = (const float*)d_in[0];
    const float* in_proj_w  = (const float*)d_in[1];
    const float* conv_w     = (const float*)d_in[2];
    const float* conv_b     = (const float*)d_in[3];
    const float* x_proj_w   = (const float*)d_in[4];
    const float* dt_proj_w  = (const float*)d_in[5];
    const float* dt_proj_b  = (const float*)d_in[6];
    const float* A_log      = (const float*)d_in[7];
    const float* Dv         = (const float*)d_in[8];
    const float* out_proj_w = (const float*)d_in[9];
    float* out = (float*)d_out;

    float* xr  = nullptr; cudaGetSymbolAddress((void**)&xr,  g_xr);
    float* u   = nullptr; cudaGetSymbolAddress((void**)&u,   g_u);
    float* dbc = nullptr; cudaGetSymbolAddress((void**)&dbc, g_dbc);
    float* dt  = nullptr; cudaGetSymbolAddress((void**)&dt,  g_dt);
    float* y   = nullptr; cudaGetSymbolAddress((void**)&y,   g_y);

    // 1) xr = x @ in_proj_w              (4096 x 4096, K=1024)
    sgemm_k<<<dim3((2 * D_INNER) / BN, NROWS / BM), 256>>>(
        x, D_MODEL, in_proj_w, nullptr, xr, NROWS, 2 * D_INNER, D_MODEL, 0);

    // 2) u = silu(causal depthwise conv(xb) + conv_b)
    {
        size_t total = (size_t)NROWS * D_INNER;
        conv_silu_k<<<(unsigned)((total + 255) / 256), 256>>>(conv_w, conv_b);
    }

    // 3) dbc = u @ x_proj_w              (4096 x 96, K=2048)
    sgemm_k<<<dim3((DBC_COLS + BN - 1) / BN, NROWS / BM), 256>>>(
        u, D_INNER, x_proj_w, nullptr, dbc, NROWS, DBC_COLS, D_INNER, 0);

    // 4) dt = softplus(dbc[:, :64] @ dt_proj_w + dt_proj_b)  (4096 x 2048, K=64)
    sgemm_k<<<dim3(D_INNER / BN, NROWS / BM), 256>>>(
        dbc, DBC_COLS, dt_proj_w, dt_proj_b, dt, NROWS, D_INNER, DT_RANK, 1);

    // 5) selective scan + gating -> y
    scan_k<<<dim3(D_INNER / 16, BATCH), 256>>>(A_log, Dv);

    // 6) out = y @ out_proj_w            (4096 x 1024, K=2048)
    sgemm_k<<<dim3(D_MODEL / BN, NROWS / BM), 256>>>(
        y, D_INNER, out_proj_w, nullptr, out, NROWS, D_MODEL, D_INNER, 0);
}

// round 2
// speedup vs baseline: 3.5744x; 3.5744x over previous
#include <cuda_runtime.h>
#include <cstdint>
#include <cstddef>

// ---------------- problem constants ----------------
#define D_MODEL  1024
#define D_STATE  16
#define D_INNER  2048
#define DT_RANK  64
#define BATCH    2
#define SEQ      2048
#define NROWS    (BATCH * SEQ)          // 4096
#define DBC_COLS (DT_RANK + 2 * D_STATE) // 96

// ---------------- scratch (static device globals; no allocation) ----------------
__device__ float g_xr [(size_t)NROWS * (2 * D_INNER)];  // cols [0,2048)=xb, [2048,4096)=res
__device__ float g_u  [(size_t)NROWS * D_INNER];
__device__ float g_dbc[(size_t)NROWS * DBC_COLS];
__device__ float g_dt [(size_t)NROWS * D_INNER];
__device__ float g_y  [(size_t)NROWS * D_INNER];

// ---------------- helpers ----------------
__device__ __forceinline__ float silu_f(float x) { return x / (1.0f + __expf(-x)); }
__device__ __forceinline__ float softplus_f(float x) { return (x > 20.0f) ? x : log1pf(__expf(x)); }
__device__ __forceinline__ unsigned tf32_of(float x) {
    unsigned r; asm("cvt.rna.tf32.f32 %0, %1;" : "=r"(r) : "f"(x)); return r;
}
__device__ __forceinline__ void mma_tf32(float* d, const unsigned* a, const unsigned* b) {
    asm volatile(
        "mma.sync.aligned.m16n8k8.row.col.f32.tf32.tf32.f32 "
        "{%0,%1,%2,%3}, {%4,%5,%6,%7}, {%8,%9}, {%0,%1,%2,%3};"
        : "+f"(d[0]), "+f"(d[1]), "+f"(d[2]), "+f"(d[3])
        : "r"(a[0]), "r"(a[1]), "r"(a[2]), "r"(a[3]), "r"(b[0]), "r"(b[1]));
}

// ---------------- tf32 tensor-core GEMM: C[M,N] = A[M,K(lda)] * B[K,N] ----------------
// mode 0: plain store. mode 1: softplus(acc + bias[col]).
#define GBM 128
#define GBN 128
#define GBK 16
#define SPAD 8   // row stride 136 floats -> 136%32==8 -> conflict-free frag reads

__global__ __launch_bounds__(256, 2) void gemm_tf32(
    const float* __restrict__ A, int lda,
    const float* __restrict__ B,
    const float* __restrict__ bias,
    float* __restrict__ C,
    int M, int N, int K, int mode)
{
    __shared__ float As[2][GBK][GBM + SPAD];
    __shared__ float Bs[2][GBK][GBN + SPAD];

    const int tid  = threadIdx.x;
    const int warp = tid >> 5;
    const int lane = tid & 31;
    const int gid  = lane >> 2;   // group id 0..7
    const int tig  = lane & 3;    // thread in group 0..3
    const int wm   = (warp & 1) * 64;  // warp M origin (2 warps in M)
    const int wn   = (warp >> 1) * 32; // warp N origin (4 warps in N)
    const int mBase = blockIdx.y * GBM;
    const int nBase = blockIdx.x * GBN;

    // global->smem staging maps
    const int aRow = tid >> 1;   // 0..127 (m)
    const int aC4  = tid & 1;    // which pair of float4 in the 16-wide k slab
    const int bRow = tid >> 4;   // 0..15 (k)
    const int bC   = tid & 15;   // float4 column group

    float acc[4][4][4];
#pragma unroll
    for (int i = 0; i < 4; i++)
#pragma unroll
        for (int j = 0; j < 4; j++)
#pragma unroll
            for (int q = 0; q < 4; q++) acc[i][j][q] = 0.0f;

    float4 ra[2], rb[2];

    auto ldgA = [&](int k0) {
#pragma unroll
        for (int v = 0; v < 2; v++)
            ra[v] = *reinterpret_cast<const float4*>(
                A + (size_t)(mBase + aRow) * lda + k0 + (aC4 * 2 + v) * 4);
    };
    auto ldgB = [&](int k0) {
#pragma unroll
        for (int v = 0; v < 2; v++) {
            int col = nBase + (bC + 16 * v) * 4;
            if (col < N)
                rb[v] = *reinterpret_cast<const float4*>(
                    B + (size_t)(k0 + bRow) * N + col);
            else
                rb[v] = make_float4(0.f, 0.f, 0.f, 0.f);
        }
    };
    auto stsA = [&](int buf) {
#pragma unroll
        for (int v = 0; v < 2; v++) {
            int kk = aC4 * 8 + v * 4;
            As[buf][kk + 0][aRow] = __uint_as_float(tf32_of(ra[v].x));
            As[buf][kk + 1][aRow] = __uint_as_float(tf32_of(ra[v].y));
            As[buf][kk + 2][aRow] = __uint_as_float(tf32_of(ra[v].z));
            As[buf][kk + 3][aRow] = __uint_as_float(tf32_of(ra[v].w));
        }
    };
    auto stsB = [&](int buf) {
#pragma unroll
        for (int v = 0; v < 2; v++) {
            float4 t;
            t.x = __uint_as_float(tf32_of(rb[v].x));
            t.y = __uint_as_float(tf32_of(rb[v].y));
            t.z = __uint_as_float(tf32_of(rb[v].z));
            t.w = __uint_as_float(tf32_of(rb[v].w));
            *reinterpret_cast<float4*>(&Bs[buf][bRow][(bC + 16 * v) * 4]) = t;
        }
    };
    auto compute = [&](int buf) {
#pragma unroll
        for (int ks = 0; ks < GBK; ks += 8) {
            unsigned af[4][4], bf[4][2];
#pragma unroll
            for (int i = 0; i < 4; i++) {
                int m0 = wm + i * 16 + gid;
                af[i][0] = __float_as_uint(As[buf][ks + tig    ][m0]);
                af[i][1] = __float_as_uint(As[buf][ks + tig    ][m0 + 8]);
                af[i][2] = __float_as_uint(As[buf][ks + tig + 4][m0]);
                af[i][3] = __float_as_uint(As[buf][ks + tig + 4][m0 + 8]);
            }
#pragma unroll
            for (int j = 0; j < 4; j++) {
                int n0 = wn + j * 8 + gid;
                bf[j][0] = __float_as_uint(Bs[buf][ks + tig    ][n0]);
                bf[j][1] = __float_as_uint(Bs[buf][ks + tig + 4][n0]);
            }
#pragma unroll
            for (int i = 0; i < 4; i++)
#pragma unroll
                for (int j = 0; j < 4; j++)
                    mma_tf32(acc[i][j], af[i], bf[j]);
        }
    };

    // prologue
    ldgA(0); ldgB(0);
    stsA(0); stsB(0);
    __syncthreads();

    const int nt = K / GBK;
    for (int t = 0; t < nt; t++) {
        const int buf = t & 1;
        const bool more = (t + 1 < nt);
        if (more) { ldgA((t + 1) * GBK); ldgB((t + 1) * GBK); }
        compute(buf);
        if (more) { stsA(buf ^ 1); stsB(buf ^ 1); }
        __syncthreads();
    }

    // epilogue
#pragma unroll
    for (int i = 0; i < 4; i++) {
        int r0 = mBase + wm + i * 16 + gid;
#pragma unroll
        for (int j = 0; j < 4; j++) {
            int cc = nBase + wn + j * 8 + tig * 2;
            if (cc < N) {
                float2 v0, v1;
                v0.x = acc[i][j][0]; v0.y = acc[i][j][1];
                v1.x = acc[i][j][2]; v1.y = acc[i][j][3];
                if (mode == 1) {
                    float b0 = bias[cc], b1 = bias[cc + 1];
                    v0.x = softplus_f(v0.x + b0); v0.y = softplus_f(v0.y + b1);
                    v1.x = softplus_f(v1.x + b0); v1.y = softplus_f(v1.y + b1);
                }
                *reinterpret_cast<float2*>(C + (size_t)r0 * N + cc)       = v0;
                *reinterpret_cast<float2*>(C + (size_t)(r0 + 8) * N + cc) = v1;
            }
        }
    }
}

// ---------------- causal depthwise conv1d + silu ----------------
__global__ void conv_silu_k(const float* __restrict__ conv_w,
                            const float* __restrict__ conv_b)
{
    size_t idx = (size_t)blockIdx.x * blockDim.x + threadIdx.x;
    if (idx >= (size_t)NROWS * D_INNER) return;
    int d = (int)(idx % D_INNER);
    int l = (int)((idx / D_INNER) % SEQ);
    int b = (int)(idx / ((size_t)D_INNER * SEQ));

    float acc = conv_b[d];
    const float w0 = conv_w[d * 4 + 0];
    const float w1 = conv_w[d * 4 + 1];
    const float w2 = conv_w[d * 4 + 2];
    const float w3 = conv_w[d * 4 + 3];
    const size_t base = ((size_t)b * SEQ) * (2 * D_INNER) + d;
    const size_t rs = 2 * D_INNER;
    if (l - 3 >= 0) acc = fmaf(g_xr[base + (size_t)(l - 3) * rs], w0, acc);
    if (l - 2 >= 0) acc = fmaf(g_xr[base + (size_t)(l - 2) * rs], w1, acc);
    if (l - 1 >= 0) acc = fmaf(g_xr[base + (size_t)(l - 1) * rs], w2, acc);
    acc = fmaf(g_xr[base + (size_t)l * rs], w3, acc);

    g_u[((size_t)b * SEQ + l) * D_INNER + d] = silu_f(acc);
}

// ---------------- selective scan (smem-chunked, double-buffered) ----------------
// Block = 16 d-channels x 16 state lanes = 256 threads. grid = (D_INNER/16, BATCH).
#define TCH 32
__global__ __launch_bounds__(256) void scan_k(
    const float* __restrict__ A_log,
    const float* __restrict__ Dv)
{
    __shared__ float s_dt [2][TCH][16];
    __shared__ float s_u  [2][TCH][16];
    __shared__ float s_res[2][TCH][16];
    __shared__ float s_bc [2][TCH][32];   // [.. ][0:16)=B, [16:32)=C
    __shared__ float s_y  [TCH][16];

    const int b    = blockIdx.y;
    const int d0   = blockIdx.x * 16;
    const int tid  = threadIdx.x;
    const int dloc = tid >> 4;
    const int n    = tid & 15;
    const int d    = d0 + dloc;

    const float Acoef = -__expf(A_log[d * D_STATE + n]);
    const float Dd    = Dv[d];
    float h = 0.0f;
    const size_t rowBase = (size_t)b * SEQ;

    auto load_chunk = [&](int l0, int buf) {
#pragma unroll
        for (int p = 0; p < 2; p++) {
            int e = p * 256 + tid, row = e >> 4, col = e & 15;
            size_t gRow = rowBase + l0 + row;
            s_dt [buf][row][col] = g_dt[gRow * D_INNER + d0 + col];
            s_u  [buf][row][col] = g_u [gRow * D_INNER + d0 + col];
            s_res[buf][row][col] = g_xr[gRow * (2 * D_INNER) + D_INNER + d0 + col];
        }
#pragma unroll
        for (int p = 0; p < 4; p++) {
            int e = p * 256 + tid, row = e >> 5, col = e & 31;
            s_bc[buf][row][col] =
                g_dbc[(rowBase + l0 + row) * DBC_COLS + DT_RANK + col];
        }
    };

    load_chunk(0, 0);
    __syncthreads();

    const int NCH = SEQ / TCH;
    for (int c = 0; c < NCH; c++) {
        const int buf = c & 1;
        if (c + 1 < NCH) load_chunk((c + 1) * TCH, buf ^ 1);

#pragma unroll 8
        for (int t = 0; t < TCH; t++) {
            float dt = s_dt[buf][t][dloc];
            float u  = s_u [buf][t][dloc];
            float Bn = s_bc[buf][t][n];
            float Cn = s_bc[buf][t][16 + n];
            float dA = __expf(dt * Acoef);
            h = fmaf(h, dA, (dt * u) * Bn);
            float v = h * Cn;
            v += __shfl_xor_sync(0xffffffffu, v, 8);
            v += __shfl_xor_sync(0xffffffffu, v, 4);
            v += __shfl_xor_sync(0xffffffffu, v, 2);
            v += __shfl_xor_sync(0xffffffffu, v, 1);
            if (n == 0) s_y[t][dloc] = fmaf(Dd, u, v);
        }
        __syncthreads();   // s_y complete; next chunk's loads complete

        // gated, coalesced y write
#pragma unroll
        for (int p = 0; p < 2; p++) {
            int e = p * 256 + tid, row = e >> 4, col = e & 15;
            float r = s_res[buf][row][col];
            g_y[(rowBase + c * TCH + row) * D_INNER + d0 + col] =
                s_y[row][col] * silu_f(r);
        }
        __syncthreads();   // s_y consumed before next chunk overwrites it
    }
}

// ---------------- launch ----------------
extern "C" void kernel_launch(void* const* d_in, const int* in_sizes, int n_in,
                              void* d_out, int out_size)
{
    const float* x          = (const float*)d_in[0];
    const float* in_proj_w  = (const float*)d_in[1];
    const float* conv_w     = (const float*)d_in[2];
    const float* conv_b     = (const float*)d_in[3];
    const float* x_proj_w   = (const float*)d_in[4];
    const float* dt_proj_w  = (const float*)d_in[5];
    const float* dt_proj_b  = (const float*)d_in[6];
    const float* A_log      = (const float*)d_in[7];
    const float* Dv         = (const float*)d_in[8];
    const float* out_proj_w = (const float*)d_in[9];
    float* out = (float*)d_out;

    float* xr  = nullptr; cudaGetSymbolAddress((void**)&xr,  g_xr);
    float* u   = nullptr; cudaGetSymbolAddress((void**)&u,   g_u);
    float* dbc = nullptr; cudaGetSymbolAddress((void**)&dbc, g_dbc);
    float* dt  = nullptr; cudaGetSymbolAddress((void**)&dt,  g_dt);
    float* y   = nullptr; cudaGetSymbolAddress((void**)&y,   g_y);

    // 1) xr = x @ in_proj_w   (4096 x 4096, K=1024)
    gemm_tf32<<<dim3((2 * D_INNER) / GBN, NROWS / GBM), 256>>>(
        x, D_MODEL, in_proj_w, nullptr, xr, NROWS, 2 * D_INNER, D_MODEL, 0);

    // 2) u = silu(causal depthwise conv(xb) + conv_b)
    {
        size_t total = (size_t)NROWS * D_INNER;
        conv_silu_k<<<(unsigned)((total + 255) / 256), 256>>>(conv_w, conv_b);
    }

    // 3) dbc = u @ x_proj_w   (4096 x 96, K=2048)
    gemm_tf32<<<dim3((DBC_COLS + GBN - 1) / GBN, NROWS / GBM), 256>>>(
        u, D_INNER, x_proj_w, nullptr, dbc, NROWS, DBC_COLS, D_INNER, 0);

    // 4) dt = softplus(dbc[:, :64] @ dt_proj_w + dt_proj_b)  (4096 x 2048, K=64)
    gemm_tf32<<<dim3(D_INNER / GBN, NROWS / GBM), 256>>>(
        dbc, DBC_COLS, dt_proj_w, dt_proj_b, dt, NROWS, D_INNER, DT_RANK, 1);

    // 5) selective scan + gating -> y
    scan_k<<<dim3(D_INNER / 16, BATCH), 256>>>(A_log, Dv);

    // 6) out = y @ out_proj_w (4096 x 1024, K=2048)
    gemm_tf32<<<dim3(D_MODEL / GBN, NROWS / GBM), 256>>>(
        y, D_INNER, out_proj_w, nullptr, out, NROWS, D_MODEL, D_INNER, 0);
}